// round 3
// baseline (speedup 1.0000x reference)
#include <cuda_runtime.h>
#include <cstdint>

#define NMAX 100000
#define EMAX 640000
#define DIM 128
#define NREL 8

// Scratch (static device globals; runtime allocation is forbidden)
__device__ float g_Yrel[(size_t)NMAX * NREL * DIM];   // per-relation transformed features [N][8][128]
__device__ float g_h[(size_t)NMAX * DIM];             // layer-1 output / layer-2 input
__device__ float g_inv[NMAX * NREL];                  // 1/max(cnt,1) per (node, rel); also used as cnt

// ---------------------------------------------------------------------------
// cnt / inv   (edge indices are int32: JAX x64 disabled downcasts int64->int32)
// ---------------------------------------------------------------------------
__global__ void zero_inv_kernel(int n8) {
    int i = blockIdx.x * blockDim.x + threadIdx.x;
    if (i < n8) g_inv[i] = 0.0f;
}

__global__ void count_kernel(const int* __restrict__ ei,
                             const int* __restrict__ et, int e) {
    int i = blockIdx.x * blockDim.x + threadIdx.x;
    if (i >= e) return;
    int dst = ei[e + i];
    int r   = et[i];
    atomicAdd(&g_inv[dst * NREL + r], 1.0f);
}

__global__ void invert_kernel(int n8) {
    int i = blockIdx.x * blockDim.x + threadIdx.x;
    if (i < n8) g_inv[i] = 1.0f / fmaxf(g_inv[i], 1.0f);
}

// ---------------------------------------------------------------------------
// GEMM: C[n, 9*128] = A[n,128] @ [root | W_0..W_7]
//   blockIdx.y == 0 : root block -> outbuf[n][c] = acc + bias[c]
//   blockIdx.y >= 1 : relation (bn-1) -> g_Yrel[n][r][c] = acc
// Tile: BM=64, BN=128, BK=32, threads=256, per-thread 4x8
// ---------------------------------------------------------------------------
__global__ __launch_bounds__(256) void gemm_kernel(
    const float* __restrict__ A, const float* __restrict__ rootw,
    const float* __restrict__ relw, const float* __restrict__ bias,
    float* __restrict__ outbuf, int nrows)
{
    __shared__ float As[32][68];   // [k][row], padded (68*4B = 17*16B keeps float4 alignment)
    __shared__ float Bs[32][128];  // [k][col]

    const int bn = blockIdx.y;
    const float* __restrict__ B =
        (bn == 0) ? rootw : (relw + (size_t)(bn - 1) * DIM * DIM);
    const int row0 = blockIdx.x * 64;
    const int tid = threadIdx.x;
    const int tx = tid & 15;   // 16 col groups of 8
    const int ty = tid >> 4;   // 16 row groups of 4

    float acc[4][8];
#pragma unroll
    for (int i = 0; i < 4; i++)
#pragma unroll
        for (int j = 0; j < 8; j++) acc[i][j] = 0.0f;

    for (int k0 = 0; k0 < DIM; k0 += 32) {
        // load A tile 64x32 (transposed into As[k][row]): 512 float4, 2 per thread
#pragma unroll
        for (int it = 0; it < 2; it++) {
            int id = tid + it * 256;
            int r  = id >> 3;      // 0..63 node row
            int c4 = id & 7;       // 0..7 float4 along k
            int grow = row0 + r;
            float4 v = make_float4(0.f, 0.f, 0.f, 0.f);
            if (grow < nrows)
                v = *(const float4*)&A[(size_t)grow * DIM + k0 + c4 * 4];
            As[c4 * 4 + 0][r] = v.x;
            As[c4 * 4 + 1][r] = v.y;
            As[c4 * 4 + 2][r] = v.z;
            As[c4 * 4 + 3][r] = v.w;
        }
        // load B tile 32x128: 1024 float4, 4 per thread
#pragma unroll
        for (int it = 0; it < 4; it++) {
            int id = tid + it * 256;
            int r  = id >> 5;      // 0..31 k row
            int c4 = id & 31;      // 0..31 float4 along col
            *(float4*)&Bs[r][c4 * 4] =
                *(const float4*)&B[(size_t)(k0 + r) * DIM + c4 * 4];
        }
        __syncthreads();

#pragma unroll
        for (int kk = 0; kk < 32; kk++) {
            float4 a4 = *(const float4*)&As[kk][ty * 4];
            float4 b0 = *(const float4*)&Bs[kk][tx * 8];
            float4 b1 = *(const float4*)&Bs[kk][tx * 8 + 4];
            float a[4] = {a4.x, a4.y, a4.z, a4.w};
            float b[8] = {b0.x, b0.y, b0.z, b0.w, b1.x, b1.y, b1.z, b1.w};
#pragma unroll
            for (int i = 0; i < 4; i++)
#pragma unroll
                for (int j = 0; j < 8; j++)
                    acc[i][j] = fmaf(a[i], b[j], acc[i][j]);
        }
        __syncthreads();
    }

    if (bn == 0) {
        float bv[8];
#pragma unroll
        for (int j = 0; j < 8; j++) bv[j] = bias[tx * 8 + j];
#pragma unroll
        for (int i = 0; i < 4; i++) {
            int grow = row0 + ty * 4 + i;
            if (grow < nrows) {
                float4 o0 = make_float4(acc[i][0] + bv[0], acc[i][1] + bv[1],
                                        acc[i][2] + bv[2], acc[i][3] + bv[3]);
                float4 o1 = make_float4(acc[i][4] + bv[4], acc[i][5] + bv[5],
                                        acc[i][6] + bv[6], acc[i][7] + bv[7]);
                *(float4*)&outbuf[(size_t)grow * DIM + tx * 8]     = o0;
                *(float4*)&outbuf[(size_t)grow * DIM + tx * 8 + 4] = o1;
            }
        }
    } else {
        int r = bn - 1;
#pragma unroll
        for (int i = 0; i < 4; i++) {
            int grow = row0 + ty * 4 + i;
            if (grow < nrows) {
                size_t base = ((size_t)grow * NREL + r) * DIM + tx * 8;
                float4 o0 = make_float4(acc[i][0], acc[i][1], acc[i][2], acc[i][3]);
                float4 o1 = make_float4(acc[i][4], acc[i][5], acc[i][6], acc[i][7]);
                *(float4*)&g_Yrel[base]     = o0;
                *(float4*)&g_Yrel[base + 4] = o1;
            }
        }
    }
}

// ---------------------------------------------------------------------------
// Edge scatter: one warp per edge; out[dst] += Yrel[src][r] * inv[dst][r]
// Vectorized reduction (red.global.add.v4.f32, sm_90+) into L2-resident out.
// ---------------------------------------------------------------------------
__global__ __launch_bounds__(256) void scatter_kernel(
    const int* __restrict__ ei, const int* __restrict__ et,
    float* __restrict__ out, int e)
{
    int g = blockIdx.x * blockDim.x + threadIdx.x;
    int warp = g >> 5;
    int lane = g & 31;
    if (warp >= e) return;
    int src = ei[warp];
    int dst = ei[e + warp];
    int r   = et[warp];
    float s = g_inv[dst * NREL + r];
    const float4 v =
        *(const float4*)&g_Yrel[(((size_t)src * NREL + r) << 7) + (lane << 2)];
    float* p = out + (size_t)dst * DIM + (lane << 2);
    asm volatile("red.global.add.v4.f32 [%0], {%1,%2,%3,%4};"
                 :: "l"(p), "f"(v.x * s), "f"(v.y * s), "f"(v.z * s), "f"(v.w * s)
                 : "memory");
}

__global__ void relu_kernel(float* __restrict__ p, int n) {
    int i = blockIdx.x * blockDim.x + threadIdx.x;
    if (i < n) p[i] = fmaxf(p[i], 0.0f);
}

// ---------------------------------------------------------------------------
// Launch
// ---------------------------------------------------------------------------
extern "C" void kernel_launch(void* const* d_in, const int* in_sizes, int n_in,
                              void* d_out, int out_size)
{
    const float* x   = (const float*)d_in[0];
    const int*   ei  = (const int*)d_in[1];  // [2,E] int32 (JAX x64 disabled)
    const int*   et  = (const int*)d_in[2];  // [E] int32
    const float* rw1 = (const float*)d_in[3];
    const float* ro1 = (const float*)d_in[4];
    const float* b1  = (const float*)d_in[5];
    const float* rw2 = (const float*)d_in[6];
    const float* ro2 = (const float*)d_in[7];
    const float* b2  = (const float*)d_in[8];
    float* out = (float*)d_out;

    const int n = in_sizes[0] / DIM;
    const int e = in_sizes[2];

    float* hptr;
    cudaGetSymbolAddress((void**)&hptr, g_h);

    const int n8 = n * NREL;
    dim3 gemm_grid((n + 63) / 64, NREL + 1);
    int scat_blocks = (e * 32 + 255) / 256;

    // shared edge statistics (same graph for both layers)
    zero_inv_kernel<<<(n8 + 255) / 256, 256>>>(n8);
    count_kernel<<<(e + 255) / 256, 256>>>(ei, et, e);
    invert_kernel<<<(n8 + 255) / 256, 256>>>(n8);

    // layer 1: h = relu(x@root1 + b1 + scatter(Y1))
    gemm_kernel<<<gemm_grid, 256>>>(x, ro1, rw1, b1, hptr, n);
    scatter_kernel<<<scat_blocks, 256>>>(ei, et, hptr, e);
    relu_kernel<<<(n * DIM + 255) / 256, 256>>>(hptr, n * DIM);

    // layer 2: out = relu(h@root2 + b2 + scatter(Y2))
    gemm_kernel<<<gemm_grid, 256>>>(hptr, ro2, rw2, b2, out, n);
    scatter_kernel<<<scat_blocks, 256>>>(ei, et, out, e);
    relu_kernel<<<(n * DIM + 255) / 256, 256>>>(out, n * DIM);
}

// round 4
// speedup vs baseline: 2.4176x; 2.4176x over previous
#include <cuda_runtime.h>
#include <cuda_bf16.h>
#include <cstdint>

#define NMAX 100000
#define DIM 128
#define NREL 8
#define ASTRIDE 136   // padded smem row stride in bf16 elems (conflict-free frags)

// Scratch (static device globals; runtime allocation is forbidden)
__device__ float g_Yrel[(size_t)NMAX * NREL * DIM];   // per-relation transformed feats
__device__ float g_h[(size_t)NMAX * DIM];             // layer-1 accumulate buffer
__device__ float g_inv[NMAX * NREL];                  // 1/max(cnt,1), also cnt
__device__ __nv_bfloat16 g_Ahi[(size_t)NMAX * DIM];   // split-precision activations
__device__ __nv_bfloat16 g_Alo[(size_t)NMAX * DIM];
__device__ __nv_bfloat16 g_Wth[2 * 9 * DIM * DIM];    // transposed [n][k] weights hi
__device__ __nv_bfloat16 g_Wtl[2 * 9 * DIM * DIM];    // lo

// ---------------------------------------------------------------------------
// cnt / inv
// ---------------------------------------------------------------------------
__global__ void zero_inv_kernel(int n8) {
    int i = blockIdx.x * blockDim.x + threadIdx.x;
    if (i < n8) g_inv[i] = 0.0f;
}

__global__ void count_kernel(const int* __restrict__ ei,
                             const int* __restrict__ et, int e) {
    int i = blockIdx.x * blockDim.x + threadIdx.x;
    if (i >= e) return;
    atomicAdd(&g_inv[ei[e + i] * NREL + et[i]], 1.0f);
}

__global__ void invert_kernel(int n8) {
    int i = blockIdx.x * blockDim.x + threadIdx.x;
    if (i < n8) g_inv[i] = 1.0f / fmaxf(g_inv[i], 1.0f);
}

// ---------------------------------------------------------------------------
// Split-precision conversions
// ---------------------------------------------------------------------------
__device__ __forceinline__ void split_bf16(float v, unsigned short& h, unsigned short& l) {
    __nv_bfloat16 bh = __float2bfloat16(v);
    float r = v - __bfloat162float(bh);
    __nv_bfloat16 bl = __float2bfloat16(r);
    h = *reinterpret_cast<unsigned short*>(&bh);
    l = *reinterpret_cast<unsigned short*>(&bl);
}

// src fp32 -> g_Ahi/g_Alo bf16, optional fused relu. nelem4 = n*DIM/4
__global__ void convert_split_kernel(const float* __restrict__ src, int nelem4, int do_relu) {
    int i = blockIdx.x * blockDim.x + threadIdx.x;
    if (i >= nelem4) return;
    float4 v = ((const float4*)src)[i];
    if (do_relu) {
        v.x = fmaxf(v.x, 0.f); v.y = fmaxf(v.y, 0.f);
        v.z = fmaxf(v.z, 0.f); v.w = fmaxf(v.w, 0.f);
    }
    ushort4 hs, ls;
    split_bf16(v.x, hs.x, ls.x);
    split_bf16(v.y, hs.y, ls.y);
    split_bf16(v.z, hs.z, ls.z);
    split_bf16(v.w, hs.w, ls.w);
    ((ushort4*)g_Ahi)[i] = hs;
    ((ushort4*)g_Alo)[i] = ls;
}

// weights [k][n] fp32 -> transposed [bn][n][k] bf16 hi/lo
__global__ void wconvert_kernel(const float* __restrict__ root,
                                const float* __restrict__ rel,
                                __nv_bfloat16* __restrict__ wth,
                                __nv_bfloat16* __restrict__ wtl) {
    int i = blockIdx.x * blockDim.x + threadIdx.x;
    if (i >= 9 * DIM * DIM) return;
    int bn = i >> 14;
    int t  = i & 16383;
    int n  = t >> 7;
    int k  = t & 127;
    float w = bn ? rel[(size_t)(bn - 1) * DIM * DIM + k * DIM + n] : root[k * DIM + n];
    unsigned short h, l;
    split_bf16(w, h, l);
    wth[i] = *reinterpret_cast<__nv_bfloat16*>(&h);
    wtl[i] = *reinterpret_cast<__nv_bfloat16*>(&l);
}

// ---------------------------------------------------------------------------
// Tensor-core GEMM (mma.sync m16n8k16 bf16, 3-product split):
//   C[64 x 128] = A_tile[64 x 128] @ W_bn^T, K=128 one-shot.
//   blockIdx.x = bn (0 = root -> outroot + bias; 1..8 -> g_Yrel[:, bn-1, :])
//   blockIdx.y = m-tile. 128 threads = 4 warps, warp tile 32x64.
// ---------------------------------------------------------------------------
#define MMA16816(d, a, b)                                                  \
    asm volatile(                                                          \
        "mma.sync.aligned.m16n8k16.row.col.f32.bf16.bf16.f32 "             \
        "{%0,%1,%2,%3},{%4,%5,%6,%7},{%8,%9},{%0,%1,%2,%3};"               \
        : "+f"(d[0]), "+f"(d[1]), "+f"(d[2]), "+f"(d[3])                   \
        : "r"(a[0]), "r"(a[1]), "r"(a[2]), "r"(a[3]), "r"(b[0]), "r"(b[1]))

__global__ __launch_bounds__(128) void gemm_mma_kernel(
    const __nv_bfloat16* __restrict__ wth,   // layer base [9][128][128] (n,k)
    const __nv_bfloat16* __restrict__ wtl,
    const float* __restrict__ bias,
    float* __restrict__ outroot, int nrows)
{
    extern __shared__ __nv_bfloat16 smem[];
    __nv_bfloat16* sAh = smem;                   // 64 x ASTRIDE
    __nv_bfloat16* sAl = sAh + 64 * ASTRIDE;
    __nv_bfloat16* sBh = sAl + 64 * ASTRIDE;     // 128 x ASTRIDE
    __nv_bfloat16* sBl = sBh + 128 * ASTRIDE;

    const int bn   = blockIdx.x;
    const int row0 = blockIdx.y * 64;
    const int tid  = threadIdx.x;
    const int lane = tid & 31;
    const int warp = tid >> 5;
    const int wm   = warp >> 1;   // 0..1 -> M offset 32*wm
    const int wn   = warp & 1;    // 0..1 -> N offset 64*wn
    const int grp  = lane >> 2;
    const int tg   = lane & 3;

    // ---- stage A tiles (hi/lo), 16B chunks, zero-fill OOB rows ----
#pragma unroll
    for (int it = 0; it < 8; it++) {
        int id = tid + it * 128;
        int r  = id >> 4;          // 0..63
        int c  = id & 15;          // 16B chunk
        int gr = row0 + r;
        uint4 vh = make_uint4(0, 0, 0, 0), vl = make_uint4(0, 0, 0, 0);
        if (gr < nrows) {
            vh = *(const uint4*)(g_Ahi + (size_t)gr * DIM + c * 8);
            vl = *(const uint4*)(g_Alo + (size_t)gr * DIM + c * 8);
        }
        *(uint4*)(sAh + r * ASTRIDE + c * 8) = vh;
        *(uint4*)(sAl + r * ASTRIDE + c * 8) = vl;
    }
    // ---- stage B (weight matrix bn), [n][k] ----
    const __nv_bfloat16* Bh = wth + (size_t)bn * DIM * DIM;
    const __nv_bfloat16* Bl = wtl + (size_t)bn * DIM * DIM;
#pragma unroll
    for (int it = 0; it < 16; it++) {
        int id = tid + it * 128;
        int r  = id >> 4;          // n row 0..127
        int c  = id & 15;
        *(uint4*)(sBh + r * ASTRIDE + c * 8) = *(const uint4*)(Bh + r * DIM + c * 8);
        *(uint4*)(sBl + r * ASTRIDE + c * 8) = *(const uint4*)(Bl + r * DIM + c * 8);
    }
    __syncthreads();

    float acc[2][8][4];
#pragma unroll
    for (int mi = 0; mi < 2; mi++)
#pragma unroll
        for (int ni = 0; ni < 8; ni++)
#pragma unroll
            for (int q = 0; q < 4; q++) acc[mi][ni][q] = 0.0f;

#pragma unroll
    for (int ks = 0; ks < 8; ks++) {
        const int k0 = ks * 16;
        unsigned ah[2][4], al[2][4];
#pragma unroll
        for (int mi = 0; mi < 2; mi++) {
            int r = wm * 32 + mi * 16 + grp;
            ah[mi][0] = *(const unsigned*)(sAh + r * ASTRIDE + k0 + 2 * tg);
            ah[mi][1] = *(const unsigned*)(sAh + (r + 8) * ASTRIDE + k0 + 2 * tg);
            ah[mi][2] = *(const unsigned*)(sAh + r * ASTRIDE + k0 + 8 + 2 * tg);
            ah[mi][3] = *(const unsigned*)(sAh + (r + 8) * ASTRIDE + k0 + 8 + 2 * tg);
            al[mi][0] = *(const unsigned*)(sAl + r * ASTRIDE + k0 + 2 * tg);
            al[mi][1] = *(const unsigned*)(sAl + (r + 8) * ASTRIDE + k0 + 2 * tg);
            al[mi][2] = *(const unsigned*)(sAl + r * ASTRIDE + k0 + 8 + 2 * tg);
            al[mi][3] = *(const unsigned*)(sAl + (r + 8) * ASTRIDE + k0 + 8 + 2 * tg);
        }
#pragma unroll
        for (int ni = 0; ni < 8; ni++) {
            int nrow = wn * 64 + ni * 8 + grp;
            unsigned bh[2], bl[2];
            bh[0] = *(const unsigned*)(sBh + nrow * ASTRIDE + k0 + 2 * tg);
            bh[1] = *(const unsigned*)(sBh + nrow * ASTRIDE + k0 + 8 + 2 * tg);
            bl[0] = *(const unsigned*)(sBl + nrow * ASTRIDE + k0 + 2 * tg);
            bl[1] = *(const unsigned*)(sBl + nrow * ASTRIDE + k0 + 8 + 2 * tg);
#pragma unroll
            for (int mi = 0; mi < 2; mi++) {
                MMA16816(acc[mi][ni], ah[mi], bh);
                MMA16816(acc[mi][ni], ah[mi], bl);
                MMA16816(acc[mi][ni], al[mi], bh);
            }
        }
    }

    // ---- epilogue ----
#pragma unroll
    for (int mi = 0; mi < 2; mi++) {
        int r0 = row0 + wm * 32 + mi * 16 + grp;
#pragma unroll
        for (int ni = 0; ni < 8; ni++) {
            int col = wn * 64 + ni * 8 + 2 * tg;
            if (bn == 0) {
                float b0 = bias[col], b1 = bias[col + 1];
                if (r0 < nrows) {
                    float2 o = make_float2(acc[mi][ni][0] + b0, acc[mi][ni][1] + b1);
                    *(float2*)&outroot[(size_t)r0 * DIM + col] = o;
                }
                if (r0 + 8 < nrows) {
                    float2 o = make_float2(acc[mi][ni][2] + b0, acc[mi][ni][3] + b1);
                    *(float2*)&outroot[(size_t)(r0 + 8) * DIM + col] = o;
                }
            } else {
                int rel = bn - 1;
                if (r0 < nrows) {
                    float2 o = make_float2(acc[mi][ni][0], acc[mi][ni][1]);
                    *(float2*)&g_Yrel[((size_t)r0 * NREL + rel) * DIM + col] = o;
                }
                if (r0 + 8 < nrows) {
                    float2 o = make_float2(acc[mi][ni][2], acc[mi][ni][3]);
                    *(float2*)&g_Yrel[((size_t)(r0 + 8) * NREL + rel) * DIM + col] = o;
                }
            }
        }
    }
}

// ---------------------------------------------------------------------------
// Edge scatter: one warp per edge; out[dst] += Yrel[src][r] * inv[dst][r]
// ---------------------------------------------------------------------------
__global__ __launch_bounds__(256) void scatter_kernel(
    const int* __restrict__ ei, const int* __restrict__ et,
    float* __restrict__ out, int e)
{
    int g = blockIdx.x * blockDim.x + threadIdx.x;
    int warp = g >> 5;
    int lane = g & 31;
    if (warp >= e) return;
    int src = ei[warp];
    int dst = ei[e + warp];
    int r   = et[warp];
    float s = g_inv[dst * NREL + r];
    const float4 v =
        *(const float4*)&g_Yrel[(((size_t)src * NREL + r) << 7) + (lane << 2)];
    float* p = out + (size_t)dst * DIM + (lane << 2);
    asm volatile("red.global.add.v4.f32 [%0], {%1,%2,%3,%4};"
                 :: "l"(p), "f"(v.x * s), "f"(v.y * s), "f"(v.z * s), "f"(v.w * s)
                 : "memory");
}

__global__ void relu_kernel(float* __restrict__ p, int n) {
    int i = blockIdx.x * blockDim.x + threadIdx.x;
    if (i < n) p[i] = fmaxf(p[i], 0.0f);
}

// ---------------------------------------------------------------------------
// Launch
// ---------------------------------------------------------------------------
extern "C" void kernel_launch(void* const* d_in, const int* in_sizes, int n_in,
                              void* d_out, int out_size)
{
    const float* x   = (const float*)d_in[0];
    const int*   ei  = (const int*)d_in[1];  // [2,E] int32
    const int*   et  = (const int*)d_in[2];  // [E]   int32
    const float* rw1 = (const float*)d_in[3];
    const float* ro1 = (const float*)d_in[4];
    const float* b1  = (const float*)d_in[5];
    const float* rw2 = (const float*)d_in[6];
    const float* ro2 = (const float*)d_in[7];
    const float* b2  = (const float*)d_in[8];
    float* out = (float*)d_out;

    const int n = in_sizes[0] / DIM;
    const int e = in_sizes[2];

    float* hptr;
    cudaGetSymbolAddress((void**)&hptr, g_h);
    __nv_bfloat16 *wth, *wtl;
    cudaGetSymbolAddress((void**)&wth, g_Wth);
    cudaGetSymbolAddress((void**)&wtl, g_Wtl);

    const int smem_bytes = (2 * 64 + 2 * 128) * ASTRIDE * 2;  // 104448
    cudaFuncSetAttribute(gemm_mma_kernel,
                         cudaFuncAttributeMaxDynamicSharedMemorySize, smem_bytes);

    const int n8 = n * NREL;
    dim3 ggrid(NREL + 1, (n + 63) / 64);   // bn-major for A-tile L2 reuse
    const int scat_blocks = (e * 32 + 255) / 256;
    const int nw = 9 * DIM * DIM;

    // shared edge statistics (same graph both layers)
    zero_inv_kernel<<<(n8 + 255) / 256, 256>>>(n8);
    count_kernel<<<(e + 255) / 256, 256>>>(ei, et, e);
    invert_kernel<<<(n8 + 255) / 256, 256>>>(n8);

    // weight + activation split conversion
    wconvert_kernel<<<(nw + 255) / 256, 256>>>(ro1, rw1, wth, wtl);
    wconvert_kernel<<<(nw + 255) / 256, 256>>>(ro2, rw2, wth + nw, wtl + nw);
    convert_split_kernel<<<(n * 32 + 255) / 256, 256>>>(x, n * 32, 0);

    // layer 1
    gemm_mma_kernel<<<ggrid, 128, smem_bytes>>>(wth, wtl, b1, hptr, n);
    scatter_kernel<<<scat_blocks, 256>>>(ei, et, hptr, e);
    convert_split_kernel<<<(n * 32 + 255) / 256, 256>>>(hptr, n * 32, 1);  // relu fused

    // layer 2
    gemm_mma_kernel<<<ggrid, 128, smem_bytes>>>(wth + nw, wtl + nw, b2, out, n);
    scatter_kernel<<<scat_blocks, 256>>>(ei, et, out, e);
    relu_kernel<<<(n * DIM + 255) / 256, 256>>>(out, n * DIM);
}

// round 5
// speedup vs baseline: 2.6041x; 1.0771x over previous
#include <cuda_runtime.h>
#include <cuda_bf16.h>
#include <cuda_fp16.h>
#include <cstdint>

#define NMAX 100000
#define DIM 128
#define NREL 8
#define AS 136   // padded smem row stride (bf16 elems); 272B rows -> conflict-free LDSM

// Scratch (static device globals; runtime allocation is forbidden)
__device__ __half g_Yh[(size_t)NMAX * NREL * DIM];    // per-relation transformed feats (fp16)
__device__ float g_h[(size_t)NMAX * DIM];             // layer-1 accumulate buffer
__device__ float g_inv[NMAX * NREL];                  // 1/max(cnt,1), also cnt
__device__ __nv_bfloat16 g_Ahi[(size_t)NMAX * DIM];   // split-precision activations
__device__ __nv_bfloat16 g_Alo[(size_t)NMAX * DIM];
__device__ __nv_bfloat16 g_Wth[2 * 9 * DIM * DIM];    // transposed [n][k] weights hi
__device__ __nv_bfloat16 g_Wtl[2 * 9 * DIM * DIM];    // lo

// ---------------------------------------------------------------------------
// cnt / inv
// ---------------------------------------------------------------------------
__global__ void zero_inv_kernel(int n8) {
    int i = blockIdx.x * blockDim.x + threadIdx.x;
    if (i < n8) g_inv[i] = 0.0f;
}

__global__ void count_kernel(const int* __restrict__ ei,
                             const int* __restrict__ et, int e) {
    int i = blockIdx.x * blockDim.x + threadIdx.x;
    if (i >= e) return;
    atomicAdd(&g_inv[ei[e + i] * NREL + et[i]], 1.0f);
}

__global__ void invert_kernel(int n8) {
    int i = blockIdx.x * blockDim.x + threadIdx.x;
    if (i < n8) g_inv[i] = 1.0f / fmaxf(g_inv[i], 1.0f);
}

// ---------------------------------------------------------------------------
// Split-precision conversions
// ---------------------------------------------------------------------------
__device__ __forceinline__ void split_bf16(float v, unsigned short& h, unsigned short& l) {
    __nv_bfloat16 bh = __float2bfloat16(v);
    float r = v - __bfloat162float(bh);
    __nv_bfloat16 bl = __float2bfloat16(r);
    h = *reinterpret_cast<unsigned short*>(&bh);
    l = *reinterpret_cast<unsigned short*>(&bl);
}

__global__ void convert_split_kernel(const float* __restrict__ src, int nelem4, int do_relu) {
    int i = blockIdx.x * blockDim.x + threadIdx.x;
    if (i >= nelem4) return;
    float4 v = ((const float4*)src)[i];
    if (do_relu) {
        v.x = fmaxf(v.x, 0.f); v.y = fmaxf(v.y, 0.f);
        v.z = fmaxf(v.z, 0.f); v.w = fmaxf(v.w, 0.f);
    }
    ushort4 hs, ls;
    split_bf16(v.x, hs.x, ls.x);
    split_bf16(v.y, hs.y, ls.y);
    split_bf16(v.z, hs.z, ls.z);
    split_bf16(v.w, hs.w, ls.w);
    ((ushort4*)g_Ahi)[i] = hs;
    ((ushort4*)g_Alo)[i] = ls;
}

// weights [k][n] fp32 -> transposed [bn][n][k] bf16 hi/lo
__global__ void wconvert_kernel(const float* __restrict__ root,
                                const float* __restrict__ rel,
                                __nv_bfloat16* __restrict__ wth,
                                __nv_bfloat16* __restrict__ wtl) {
    int i = blockIdx.x * blockDim.x + threadIdx.x;
    if (i >= 9 * DIM * DIM) return;
    int bn = i >> 14;
    int t  = i & 16383;
    int n  = t >> 7;
    int k  = t & 127;
    float w = bn ? rel[(size_t)(bn - 1) * DIM * DIM + k * DIM + n] : root[k * DIM + n];
    unsigned short h, l;
    split_bf16(w, h, l);
    wth[i] = *reinterpret_cast<__nv_bfloat16*>(&h);
    wtl[i] = *reinterpret_cast<__nv_bfloat16*>(&l);
}

// ---------------------------------------------------------------------------
// Tensor-core GEMM (mma m16n8k16 bf16, 3-product split), ldmatrix fragments.
//   Tile: M=128 x N=128 x K=128 one-shot. 256 threads = 8 warps (4 wm x 2 wn),
//   warp tile 32x64. blockIdx.x = bn (0 root->fp32+bias; 1..8 -> g_Yh fp16).
// ---------------------------------------------------------------------------
#define MMA16816(d, a, b)                                                  \
    asm volatile(                                                          \
        "mma.sync.aligned.m16n8k16.row.col.f32.bf16.bf16.f32 "             \
        "{%0,%1,%2,%3},{%4,%5,%6,%7},{%8,%9},{%0,%1,%2,%3};"               \
        : "+f"(d[0]), "+f"(d[1]), "+f"(d[2]), "+f"(d[3])                   \
        : "r"(a[0]), "r"(a[1]), "r"(a[2]), "r"(a[3]), "r"(b[0]), "r"(b[1]))

#define LDSM4(R, ADDR)                                                     \
    asm volatile("ldmatrix.sync.aligned.m8n8.x4.shared.b16 "               \
                 "{%0,%1,%2,%3}, [%4];"                                    \
                 : "=r"(R[0]), "=r"(R[1]), "=r"(R[2]), "=r"(R[3])          \
                 : "r"(ADDR))

__global__ __launch_bounds__(256) void gemm_mma_kernel(
    const __nv_bfloat16* __restrict__ wth,   // layer base [9][128][128] (n,k)
    const __nv_bfloat16* __restrict__ wtl,
    const float* __restrict__ bias,
    float* __restrict__ outroot, int nrows)
{
    extern __shared__ __nv_bfloat16 smem[];
    __nv_bfloat16* sAh = smem;                   // 128 x AS
    __nv_bfloat16* sAl = sAh + 128 * AS;
    __nv_bfloat16* sBh = sAl + 128 * AS;         // 128 x AS
    __nv_bfloat16* sBl = sBh + 128 * AS;

    const int bn   = blockIdx.x;
    const int row0 = blockIdx.y * 128;
    const int tid  = threadIdx.x;
    const int lane = tid & 31;
    const int warp = tid >> 5;
    const int wm   = warp & 3;    // M offset 32*wm
    const int wn   = warp >> 2;   // N offset 64*wn
    const int grp  = lane >> 2;
    const int tg   = lane & 3;

    // ---- stage A tiles (hi/lo), 16B chunks, zero-fill OOB rows ----
#pragma unroll
    for (int it = 0; it < 8; it++) {
        int id = tid + it * 256;
        int r  = id >> 4;          // 0..127
        int c  = id & 15;
        int gr = row0 + r;
        uint4 vh = make_uint4(0, 0, 0, 0), vl = make_uint4(0, 0, 0, 0);
        if (gr < nrows) {
            vh = *(const uint4*)(g_Ahi + (size_t)gr * DIM + c * 8);
            vl = *(const uint4*)(g_Alo + (size_t)gr * DIM + c * 8);
        }
        *(uint4*)(sAh + r * AS + c * 8) = vh;
        *(uint4*)(sAl + r * AS + c * 8) = vl;
    }
    // ---- stage B (weight matrix bn), [n][k] ----
    const __nv_bfloat16* Bh = wth + (size_t)bn * DIM * DIM;
    const __nv_bfloat16* Bl = wtl + (size_t)bn * DIM * DIM;
#pragma unroll
    for (int it = 0; it < 8; it++) {
        int id = tid + it * 256;
        int r  = id >> 4;
        int c  = id & 15;
        *(uint4*)(sBh + r * AS + c * 8) = *(const uint4*)(Bh + r * DIM + c * 8);
        *(uint4*)(sBl + r * AS + c * 8) = *(const uint4*)(Bl + r * DIM + c * 8);
    }
    __syncthreads();

    // ldmatrix lane addressing (byte offsets into smem window)
    const unsigned sAhB = (unsigned)__cvta_generic_to_shared(sAh);
    const unsigned sAlB = (unsigned)__cvta_generic_to_shared(sAl);
    const unsigned sBhB = (unsigned)__cvta_generic_to_shared(sBh);
    const unsigned sBlB = (unsigned)__cvta_generic_to_shared(sBl);
    // A: tiles (m0..m0+7,k0),(m0+8..,k0),(m0..,k0+8),(m0+8..,k0+8)
    const unsigned aoff = (unsigned)(((wm * 32 + (lane & 15)) * AS +
                                      ((lane >> 4) << 3)) * 2);
    // B: tiles (n0+p16..,k0),(...,k0+8),(n0+p16+8..,k0),(...,k0+8)
    const unsigned boff = (unsigned)(((wn * 64 + ((lane >> 4) << 3) + (lane & 7)) * AS +
                                      (((lane >> 3) & 1) << 3)) * 2);

    float acc[2][8][4];
#pragma unroll
    for (int mi = 0; mi < 2; mi++)
#pragma unroll
        for (int ni = 0; ni < 8; ni++)
#pragma unroll
            for (int q = 0; q < 4; q++) acc[mi][ni][q] = 0.0f;

#pragma unroll
    for (int ks = 0; ks < 8; ks++) {
        const unsigned kb = ks * 32;   // 16 elems * 2B
        unsigned ah[2][4], al[2][4];
#pragma unroll
        for (int mi = 0; mi < 2; mi++) {
            unsigned d = aoff + mi * (16 * AS * 2) + kb;
            LDSM4(ah[mi], sAhB + d);
            LDSM4(al[mi], sAlB + d);
        }
        unsigned bh[8][2], bl[8][2];
#pragma unroll
        for (int p = 0; p < 4; p++) {
            unsigned d = boff + p * (16 * AS * 2) + kb;
            unsigned th[4], tl[4];
            LDSM4(th, sBhB + d);
            LDSM4(tl, sBlB + d);
            bh[2 * p][0] = th[0]; bh[2 * p][1] = th[1];
            bh[2 * p + 1][0] = th[2]; bh[2 * p + 1][1] = th[3];
            bl[2 * p][0] = tl[0]; bl[2 * p][1] = tl[1];
            bl[2 * p + 1][0] = tl[2]; bl[2 * p + 1][1] = tl[3];
        }
#pragma unroll
        for (int ni = 0; ni < 8; ni++)
#pragma unroll
            for (int mi = 0; mi < 2; mi++) {
                MMA16816(acc[mi][ni], ah[mi], bh[ni]);
                MMA16816(acc[mi][ni], ah[mi], bl[ni]);
                MMA16816(acc[mi][ni], al[mi], bh[ni]);
            }
    }

    // ---- epilogue ----
#pragma unroll
    for (int mi = 0; mi < 2; mi++) {
        int r0 = row0 + wm * 32 + mi * 16 + grp;
#pragma unroll
        for (int ni = 0; ni < 8; ni++) {
            int col = wn * 64 + ni * 8 + 2 * tg;
            if (bn == 0) {
                float b0 = bias[col], b1 = bias[col + 1];
                if (r0 < nrows) {
                    float2 o = make_float2(acc[mi][ni][0] + b0, acc[mi][ni][1] + b1);
                    *(float2*)&outroot[(size_t)r0 * DIM + col] = o;
                }
                if (r0 + 8 < nrows) {
                    float2 o = make_float2(acc[mi][ni][2] + b0, acc[mi][ni][3] + b1);
                    *(float2*)&outroot[(size_t)(r0 + 8) * DIM + col] = o;
                }
            } else {
                int rel = bn - 1;
                if (r0 < nrows) {
                    __half2 o = __floats2half2_rn(acc[mi][ni][0], acc[mi][ni][1]);
                    *(__half2*)&g_Yh[((size_t)r0 * NREL + rel) * DIM + col] = o;
                }
                if (r0 + 8 < nrows) {
                    __half2 o = __floats2half2_rn(acc[mi][ni][2], acc[mi][ni][3]);
                    *(__half2*)&g_Yh[((size_t)(r0 + 8) * NREL + rel) * DIM + col] = o;
                }
            }
        }
    }
}

// ---------------------------------------------------------------------------
// Edge scatter: one warp per edge; out[dst] += Yh[src][r] * inv[dst][r]
// fp16 gather (8B/lane) -> fp32 vectorized reduction (16B/lane).
// ---------------------------------------------------------------------------
__global__ __launch_bounds__(256) void scatter_kernel(
    const int* __restrict__ ei, const int* __restrict__ et,
    float* __restrict__ out, int e)
{
    int g = blockIdx.x * blockDim.x + threadIdx.x;
    int warp = g >> 5;
    int lane = g & 31;
    if (warp >= e) return;
    int src = ei[warp];
    int dst = ei[e + warp];
    int r   = et[warp];
    float s = g_inv[dst * NREL + r];
    const uint2 v =
        *(const uint2*)(g_Yh + (((size_t)src * NREL + r) << 7) + (lane << 2));
    float2 f0 = __half22float2(*reinterpret_cast<const __half2*>(&v.x));
    float2 f1 = __half22float2(*reinterpret_cast<const __half2*>(&v.y));
    float* p = out + (size_t)dst * DIM + (lane << 2);
    asm volatile("red.global.add.v4.f32 [%0], {%1,%2,%3,%4};"
                 :: "l"(p), "f"(f0.x * s), "f"(f0.y * s), "f"(f1.x * s), "f"(f1.y * s)
                 : "memory");
}

__global__ void relu_kernel(float* __restrict__ p, int n) {
    int i = blockIdx.x * blockDim.x + threadIdx.x;
    if (i < n) p[i] = fmaxf(p[i], 0.0f);
}

// ---------------------------------------------------------------------------
// Launch
// ---------------------------------------------------------------------------
extern "C" void kernel_launch(void* const* d_in, const int* in_sizes, int n_in,
                              void* d_out, int out_size)
{
    const float* x   = (const float*)d_in[0];
    const int*   ei  = (const int*)d_in[1];  // [2,E] int32
    const int*   et  = (const int*)d_in[2];  // [E]   int32
    const float* rw1 = (const float*)d_in[3];
    const float* ro1 = (const float*)d_in[4];
    const float* b1  = (const float*)d_in[5];
    const float* rw2 = (const float*)d_in[6];
    const float* ro2 = (const float*)d_in[7];
    const float* b2  = (const float*)d_in[8];
    float* out = (float*)d_out;

    const int n = in_sizes[0] / DIM;
    const int e = in_sizes[2];

    float* hptr;
    cudaGetSymbolAddress((void**)&hptr, g_h);
    __nv_bfloat16 *wth, *wtl;
    cudaGetSymbolAddress((void**)&wth, g_Wth);
    cudaGetSymbolAddress((void**)&wtl, g_Wtl);

    const int smem_bytes = 4 * 128 * AS * 2;   // 139264
    static bool attr_done = false;
    if (!attr_done) {
        cudaFuncSetAttribute(gemm_mma_kernel,
                             cudaFuncAttributeMaxDynamicSharedMemorySize, smem_bytes);
        attr_done = true;
    }

    const int n8 = n * NREL;
    dim3 ggrid(NREL + 1, (n + 127) / 128);
    const int scat_blocks = (e * 32 + 255) / 256;
    const int nw = 9 * DIM * DIM;

    // shared edge statistics (same graph both layers)
    zero_inv_kernel<<<(n8 + 255) / 256, 256>>>(n8);
    count_kernel<<<(e + 255) / 256, 256>>>(ei, et, e);
    invert_kernel<<<(n8 + 255) / 256, 256>>>(n8);

    // weight + activation split conversion
    wconvert_kernel<<<(nw + 255) / 256, 256>>>(ro1, rw1, wth, wtl);
    wconvert_kernel<<<(nw + 255) / 256, 256>>>(ro2, rw2, wth + nw, wtl + nw);
    convert_split_kernel<<<(n * 32 + 255) / 256, 256>>>(x, n * 32, 0);

    // layer 1
    gemm_mma_kernel<<<ggrid, 256, smem_bytes>>>(wth, wtl, b1, hptr, n);
    scatter_kernel<<<scat_blocks, 256>>>(ei, et, hptr, e);
    convert_split_kernel<<<(n * 32 + 255) / 256, 256>>>(hptr, n * 32, 1);  // relu fused

    // layer 2
    gemm_mma_kernel<<<ggrid, 256, smem_bytes>>>(wth + nw, wtl + nw, b2, out, n);
    scatter_kernel<<<scat_blocks, 256>>>(ei, et, out, e);
    relu_kernel<<<(n * DIM + 255) / 256, 256>>>(out, n * DIM);
}